// round 9
// baseline (speedup 1.0000x reference)
#include <cuda_runtime.h>
#include <math.h>

#define NC 1000
#define NA 64
#define NT 128          // solver threads (4 warps)
#define KPT 8           // classes per thread, stride-NT layout

// Scratch for pp = rowsum(W * P). __device__ global (no allocation allowed).
__device__ float g_pp[1024];

// Kernel 1: pp[row] = sum_k W[row,k] * P[row,k].  One warp per row, float2 per
// lane, fixed-order shuffle tree => deterministic. 125 blocks -> full-chip BW.
__global__ void pp_kernel(const float* __restrict__ W, const float* __restrict__ P) {
    int warp = (blockIdx.x * blockDim.x + threadIdx.x) >> 5;
    int lane = threadIdx.x & 31;
    if (warp >= NC) return;
    const float2* w2 = reinterpret_cast<const float2*>(W + warp * NA);
    const float2* p2 = reinterpret_cast<const float2*>(P + warp * NA);
    float2 w = w2[lane];
    float2 p = p2[lane];
    float s = w.x * p.x + w.y * p.y;
    #pragma unroll
    for (int off = 16; off; off >>= 1)
        s += __shfl_down_sync(0xffffffffu, s, off);
    if (lane == 0) g_pp[warp] = s;
}

// Kernel 2: 4-warp solver (128 threads, 8 classes/thread, stride-128).
//   Minimal barrier population; single-stage warp reductions + per-thread
//   combine of 4 partials; omega table via parallel predicated FADD chains;
//   closed-form theta* start index; exact reference-loop walk (~3 steps).
__global__ __launch_bounds__(NT) void solve_kernel(const float* __restrict__ p0,
                                                   const float* __restrict__ omega,
                                                   float* __restrict__ out) {
    __shared__ float red_max[4], red_pv[4], red_pw[4], red_sum[4], red_th[4];
    __shared__ int   red_pi[4];
    __shared__ unsigned s_ball[4];
    __shared__ float som[NT];

    const unsigned FULL = 0xffffffffu;
    int tid  = threadIdx.x;
    int lane = tid & 31;
    int wid  = tid >> 5;

    float w0 = omega[0];
    w0 = fminf(fmaxf(w0, 0.0f), 1.0f);

    // ---- Omega table: thread j holds omega_j (exact float recurrence via
    //      predicated unrolled FADD chain; dependent 127x4cyc, hidden below).
    {
        float cur = w0;
        #pragma unroll
        for (int k = 0; k < NT - 1; ++k)
            if (k < tid) cur -= 0.01f;
        som[tid] = cur;
        unsigned b = __ballot_sync(FULL, (cur - 0.01f) < 0.001f);
        if (lane == 0) s_ball[wid] = b;
    }

    // ---- Loads: class j = k*NT + tid (coalesced; 1 line per warp per k) ----
    float p0v[KPT], ppv[KPT];
    #pragma unroll
    for (int k = 0; k < KPT; ++k) {
        int j = k * NT + tid;
        bool lv = (j < NC);
        p0v[k] = lv ? p0[j]   : -INFINITY;
        ppv[k] = lv ? g_pp[j] : -INFINITY;
    }

    // ---- Phase A: max(pp) + argmax(p0) carrying pp[c] ----
    float lm = -INFINITY, lav = -INFINITY, law = 0.0f;
    int   lai = 0x7fffffff;
    #pragma unroll
    for (int k = 0; k < KPT; ++k) {
        lm = fmaxf(lm, ppv[k]);
        if (p0v[k] > lav) { lav = p0v[k]; lai = k * NT + tid; law = ppv[k]; }
        // k ascending => strictly increasing j per thread: '>' keeps first index
    }
    #pragma unroll
    for (int off = 16; off; off >>= 1) {
        lm = fmaxf(lm, __shfl_down_sync(FULL, lm, off));
        float ov = __shfl_down_sync(FULL, lav, off);
        int   oi = __shfl_down_sync(FULL, lai, off);
        float ow = __shfl_down_sync(FULL, law, off);
        if (ov > lav || (ov == lav && oi < lai)) { lav = ov; lai = oi; law = ow; }
    }
    if (lane == 0) { red_max[wid] = lm; red_pv[wid] = lav; red_pi[wid] = lai; red_pw[wid] = law; }
    __syncthreads();   // also publishes som / s_ball

    float maxpp = -INFINITY, p0c = -INFINITY, ppc = 0.0f;
    int   c = 0x7fffffff;
    #pragma unroll
    for (int w = 0; w < 4; ++w) {
        maxpp = fmaxf(maxpp, red_max[w]);
        float ov = red_pv[w]; int oi = red_pi[w];
        if (ov > p0c || (ov == p0c && oi < c)) { p0c = ov; c = oi; ppc = red_pw[w]; }
    }

    // ---- Phase B: sum(exp(pp - max)) via fast exp ----
    float e[KPT];
    float ls = 0.0f;
    #pragma unroll
    for (int k = 0; k < KPT; ++k) {
        e[k] = (k * NT + tid < NC) ? __expf(ppv[k] - maxpp) : 0.0f;
        ls += e[k];
    }
    #pragma unroll
    for (int off = 16; off; off >>= 1)
        ls += __shfl_down_sync(FULL, ls, off);
    if (lane == 0) red_sum[wid] = ls;
    __syncthreads();
    float sumexp = ((red_sum[0] + red_sum[1]) + red_sum[2]) + red_sum[3];  // fixed order

    float qv[KPT];
    #pragma unroll
    for (int k = 0; k < KPT; ++k) qv[k] = e[k] / sumexp;
    float qc = __expf(ppc - maxpp) / sumexp;   // bitwise == owner's qv

    // ---- Phase C: theta* = min_j crossover(j) (linear beat condition) ----
    float lth = INFINITY;
    #pragma unroll
    for (int k = 0; k < KPT; ++k) {
        int j = k * NT + tid;
        if (j < NC && j != c) {
            float A = p0c - p0v[k];             // >= 0
            float B = qc  - qv[k];
            bool cross = (j < c) ? (B <= 0.0f) : (B < 0.0f);
            if (cross) lth = fminf(lth, A / (A - B));
        }
    }
    #pragma unroll
    for (int off = 16; off; off >>= 1)
        lth = fminf(lth, __shfl_down_sync(FULL, lth, off));
    if (lane == 0) red_th[wid] = lth;
    __syncthreads();
    float theta = fminf(fminf(red_th[0], red_th[1]), fminf(red_th[2], red_th[3]));

    // ---- Start index (computed redundantly by every thread; no serial hop) --
    int nm1 = NT - 1;                 // underflow index: first j with dec < 0.001f
    #pragma unroll
    for (int w = 0; w < 4; ++w) {
        unsigned b = s_ball[w];
        if (b) { nm1 = w * 32 + __ffs(b) - 1; break; }
    }
    int i0 = 0;
    if (isfinite(theta) && theta < w0) {
        int ie = (int)ceilf((w0 - theta) * 100.0f) - 2;   // safety margin
        i0 = (ie > 0) ? ie : 0;
    }
    i0 = (i0 < nm1) ? i0 : nm1;

    // ---- Exact reference-loop walk (match first, then underflow; ~3 steps) --
    float omstar = w0;
    {
        int i = i0;
        #pragma unroll 1
        for (int it = 0; it < NT; ++it) {
            float cw   = som[i];                 // uniform broadcast LDS
            float onem = 1.0f - cw;
            float vc = onem * p0c + cw * qc;
            int viol = 0;
            #pragma unroll
            for (int k = 0; k < KPT; ++k) {
                int j = k * NT + tid;
                if (j < NC && j != c) {
                    float vj = onem * p0v[k] + cw * qv[k];
                    viol |= (j < c) ? (vj >= vc) : (vj > vc);
                }
            }
            int any = __syncthreads_or(viol);
            omstar = cw;
            if (!any) break;                     // match: argmax == c
            if ((cw - 0.01f) < 0.001f) break;    // forced underflow stop
            ++i;
        }
    }

    // ---- Output: p = (1-omega*) * p0 + omega* * q, shape (1, NC) ----
    #pragma unroll
    for (int k = 0; k < KPT; ++k) {
        int j = k * NT + tid;
        if (j < NC)
            out[j] = (1.0f - omstar) * p0v[k] + omstar * qv[k];
    }
}

extern "C" void kernel_launch(void* const* d_in, const int* in_sizes, int n_in,
                              void* d_out, int out_size) {
    const float* p0 = (const float*)d_in[0];
    const float* P  = (const float*)d_in[1];
    const float* W  = (const float*)d_in[2];
    const float* om = (const float*)d_in[3];
    float* out = (float*)d_out;

    pp_kernel<<<125, 256>>>(W, P);
    solve_kernel<<<1, NT>>>(p0, om, out);
}

// round 10
// speedup vs baseline: 1.0563x; 1.0563x over previous
#include <cuda_runtime.h>
#include <math.h>

#define NC 1000
#define NA 64
#define NT 512          // solver threads (16 warps)
#define KPT 2           // classes per thread, stride-NT layout

// Scratch. __device__ globals (no allocation allowed).
__device__ float g_pp[1024];
__device__ float g_som[128];

// Kernel 1: blocks 0..124: pp[row] = sum_k W[row,k]*P[row,k] (warp per row).
//           block 125:     omega table g_som[j] = j exact float steps of
//                          (cur -= 0.01f)  — predicated FADD chain, runs
//                          concurrently with the other blocks' DRAM time.
__global__ void pp_kernel(const float* __restrict__ W, const float* __restrict__ P,
                          const float* __restrict__ omega) {
    if (blockIdx.x == 125) {
        int t = threadIdx.x;
        if (t < 128) {
            float w0 = omega[0];
            w0 = fminf(fmaxf(w0, 0.0f), 1.0f);
            float cur = w0;
            #pragma unroll
            for (int k = 0; k < 127; ++k)
                if (k < t) cur -= 0.01f;     // exact float recurrence
            g_som[t] = cur;
        }
        return;
    }
    int warp = (blockIdx.x * blockDim.x + threadIdx.x) >> 5;
    int lane = threadIdx.x & 31;
    if (warp >= NC) return;
    const float2* w2 = reinterpret_cast<const float2*>(W + warp * NA);
    const float2* p2 = reinterpret_cast<const float2*>(P + warp * NA);
    float2 w = w2[lane];
    float2 p = p2[lane];
    float s = w.x * p.x + w.y * p.y;
    #pragma unroll
    for (int off = 16; off; off >>= 1)
        s += __shfl_down_sync(0xffffffffu, s, off);
    if (lane == 0) g_pp[warp] = s;
}

// Kernel 2: lean 16-warp solver, ~4 barriers total.
//   q = exp(pp)/sum(exp(pp))  (pp tiny => no max-subtract needed; ~1ulp vs ref)
//   c = argmax(p0) fused into the SAME reduction phase as sum(exp).
//   theta* = min_j crossover (beat condition linear in omega).
//   Windowed exact walk: 8 omega-steps verified per barrier (REDUX.OR mask),
//   match-before-underflow ordering preserved.
__global__ __launch_bounds__(NT) void solve_kernel(const float* __restrict__ p0,
                                                   float* __restrict__ out) {
    __shared__ float red_pv[16], red_pw[16], red_sum[16], red_th[16];
    __shared__ int   red_pi[16];
    __shared__ unsigned red_m[16];
    __shared__ unsigned s_ball[4];
    __shared__ float som[128];

    const unsigned FULL = 0xffffffffu;
    int tid  = threadIdx.x;
    int lane = tid & 31;
    int wid  = tid >> 5;

    // ---- Early loads (independent; hidden under each other) ----
    if (tid < 128) {
        float v = g_som[tid];
        som[tid] = v;
        unsigned b = __ballot_sync(FULL, (v - 0.01f) < 0.001f);
        if (lane == 0) s_ball[wid] = b;
    }
    float p0v[KPT], ppv[KPT];
    #pragma unroll
    for (int k = 0; k < KPT; ++k) {
        int j = k * NT + tid;
        bool lv = (j < NC);
        p0v[k] = lv ? p0[j]   : -INFINITY;
        ppv[k] = lv ? g_pp[j] : 0.0f;
    }

    // ---- Phase A (fused): argmax(p0) carrying pp[c]  +  sum(exp(pp)) ----
    float lav = -INFINITY, law = 0.0f, ls = 0.0f;
    int   lai = 0x7fffffff;
    float e[KPT];
    #pragma unroll
    for (int k = 0; k < KPT; ++k) {
        int j = k * NT + tid;
        e[k] = (j < NC) ? __expf(ppv[k]) : 0.0f;
        ls += e[k];
        if (p0v[k] > lav) { lav = p0v[k]; lai = j; law = ppv[k]; }
        // k ascending => ascending j per thread: '>' keeps first index
    }
    #pragma unroll
    for (int off = 16; off; off >>= 1) {
        ls += __shfl_down_sync(FULL, ls, off);
        float ov = __shfl_down_sync(FULL, lav, off);
        int   oi = __shfl_down_sync(FULL, lai, off);
        float ow = __shfl_down_sync(FULL, law, off);
        if (ov > lav || (ov == lav && oi < lai)) { lav = ov; lai = oi; law = ow; }
    }
    if (lane == 0) { red_sum[wid] = ls; red_pv[wid] = lav; red_pi[wid] = lai; red_pw[wid] = law; }
    __syncthreads();   // also publishes som / s_ball

    float sumexp = 0.0f, p0c = -INFINITY, ppc = 0.0f;
    int   c = 0x7fffffff;
    #pragma unroll
    for (int w = 0; w < 16; ++w) {
        sumexp += red_sum[w];                       // fixed order => deterministic
        float ov = red_pv[w]; int oi = red_pi[w];
        if (ov > p0c || (ov == p0c && oi < c)) { p0c = ov; c = oi; ppc = red_pw[w]; }
    }

    float qv[KPT];
    #pragma unroll
    for (int k = 0; k < KPT; ++k) qv[k] = e[k] / sumexp;
    float qc = __expf(ppc) / sumexp;                // bitwise == owner's qv

    // ---- Phase B: theta* = min_j crossover(j) ----
    // beat(j over c): j<c needs d<=0, j>c needs d<0, d=(1-w)A + wB, A=p0c-p0j>=0, B=qc-qj.
    float lth = INFINITY;
    #pragma unroll
    for (int k = 0; k < KPT; ++k) {
        int j = k * NT + tid;
        if (j < NC && j != c) {
            float A = p0c - p0v[k];
            float B = qc  - qv[k];
            bool cross = (j < c) ? (B <= 0.0f) : (B < 0.0f);
            if (cross) lth = fminf(lth, A / (A - B));
        }
    }
    #pragma unroll
    for (int off = 16; off; off >>= 1)
        lth = fminf(lth, __shfl_down_sync(FULL, lth, off));
    if (lane == 0) red_th[wid] = lth;
    __syncthreads();
    float theta = INFINITY;
    #pragma unroll
    for (int w = 0; w < 16; ++w) theta = fminf(theta, red_th[w]);

    // ---- Start index (redundant per-thread; uniform) ----
    float w0 = som[0];
    int nm1 = 127;                                  // underflow index
    #pragma unroll
    for (int w = 0; w < 4; ++w) {
        unsigned b = s_ball[w];
        if (b) { nm1 = w * 32 + __ffs(b) - 1; break; }
    }
    int i0 = 0;
    if (isfinite(theta) && theta < w0) {
        int ie = (int)ceilf((w0 - theta) * 100.0f) - 3;   // window covers ie-3..ie+4
        i0 = (ie > 0) ? ie : 0;
    }
    i0 = (i0 < nm1) ? i0 : nm1;

    // ---- Windowed exact walk: 8 steps per barrier ----
    float omstar = w0;
    int i = i0;
    #pragma unroll 1
    for (int guard = 0; guard < 16; ++guard) {
        unsigned mask = 0;
        #pragma unroll
        for (int s = 0; s < 8; ++s) {
            int ii = i + s;
            int ic = (ii < 128) ? ii : 127;
            float cw   = som[ic];
            float onem = 1.0f - cw;
            float vc = onem * p0c + cw * qc;
            int v = 0;
            #pragma unroll
            for (int k = 0; k < KPT; ++k) {
                int j = k * NT + tid;
                if (j < NC && j != c) {
                    float vj = onem * p0v[k] + cw * qv[k];
                    v |= (j < c) ? (vj >= vc) : (vj > vc);
                }
            }
            if (v && ii <= nm1) mask |= (1u << s);
        }
        unsigned wm = __reduce_or_sync(FULL, mask);
        if (lane == 0) red_m[wid] = wm;
        __syncthreads();
        unsigned any = 0;
        #pragma unroll
        for (int w = 0; w < 16; ++w) any |= red_m[w];

        int stop = -1;
        #pragma unroll
        for (int s = 0; s < 8; ++s) {
            int ii = i + s;
            if (stop < 0 && ii <= nm1) {
                if (!((any >> s) & 1u)) stop = ii;      // match: argmax == c
                else if (ii == nm1)     stop = ii;      // forced underflow stop
            }
        }
        if (stop >= 0) { omstar = som[stop]; break; }
        i += 8;
        __syncthreads();    // protect red_m reuse next window (rare path)
    }

    // ---- Output: p = (1-omega*) * p0 + omega* * q, shape (1, NC) ----
    #pragma unroll
    for (int k = 0; k < KPT; ++k) {
        int j = k * NT + tid;
        if (j < NC)
            out[j] = (1.0f - omstar) * p0v[k] + omstar * qv[k];
    }
}

extern "C" void kernel_launch(void* const* d_in, const int* in_sizes, int n_in,
                              void* d_out, int out_size) {
    const float* p0 = (const float*)d_in[0];
    const float* P  = (const float*)d_in[1];
    const float* W  = (const float*)d_in[2];
    const float* om = (const float*)d_in[3];
    float* out = (float*)d_out;

    pp_kernel<<<126, 256>>>(W, P, om);
    solve_kernel<<<1, NT>>>(p0, out);
}